// round 8
// baseline (speedup 1.0000x reference)
#include <cuda_runtime.h>
#include <stdint.h>

// MeanAggregator: out[b, :] = mean over {neighbours[b,0..9], nodes[b]} of features[idx, :]
// B = 100000, K = 10, N = 1000000, D = 128 (fp32). Indices int32 (JAX x64 disabled).
//
// Quarter D-split: per-pass distinct-row footprint 667k x 128 B = 85 MB < L2 (126 MB),
// so repeat row refs hit L2 (verified ~414 MB DRAM vs 563 MB naive). DRAM util is
// capped ~69% by random-128B page locality (measured R6/R7) -> remaining lever is
// traffic: indices (4.4 MB, re-read by all 4 passes) now use DEFAULT cache policy so
// passes 1-3 hit L2 instead of re-missing (was __ldcs / evict-first).
//
// Warp handles 4 (row, quarter) pairs: 4 subgroups of 8 lanes, lane = float4 slot.
// Every gather is a coalesced LDG.128; 11 front-batched per lane for max MLP.

#define B_NODES   100000
#define K_NEIGH   10
#define D_DIM     128
#define D_VEC     (D_DIM / 4)    // 32 float4 per row
#define Q_VEC     8              // 8 float4 per quarter

__global__ __launch_bounds__(256, 4)
void mean_agg_kernel(const int*    __restrict__ nodes,
                     const int*    __restrict__ neighbours,
                     const float4* __restrict__ features,
                     float4*       __restrict__ out)
{
    const int warp = (blockIdx.x * blockDim.x + threadIdx.x) >> 5;  // 0..24999
    const int lane = threadIdx.x & 31;
    const int sub  = lane >> 3;        // subgroup 0..3 -> row offset
    const int sl   = lane & 7;         // float4 slot within quarter
    const int q    = blockIdx.y;       // feature-dim quarter (slowest-varying)

    const int row = warp * 4 + sub;
    if (row >= B_NODES) return;

    // 11 row indices (default cache policy: reused by all 4 quarter-passes -> keep in L2).
    int idx[K_NEIGH + 1];
#pragma unroll
    for (int k = 0; k < K_NEIGH; ++k)
        idx[k] = __ldg(&neighbours[row * K_NEIGH + k]);
    idx[K_NEIGH] = __ldg(&nodes[row]);

    const float4* fq = features + q * Q_VEC + sl;

    // Front-batch 11 independent LDG.128 gathers for max MLP.
    float4 v[K_NEIGH + 1];
#pragma unroll
    for (int k = 0; k < K_NEIGH + 1; ++k)
        v[k] = __ldg(fq + (long long)idx[k] * D_VEC);

    float4 acc = make_float4(0.f, 0.f, 0.f, 0.f);
#pragma unroll
    for (int k = 0; k < K_NEIGH + 1; ++k) {
        acc.x += v[k].x;
        acc.y += v[k].y;
        acc.z += v[k].z;
        acc.w += v[k].w;
    }

    const float s = 1.0f / (float)(K_NEIGH + 1);
    acc.x *= s; acc.y *= s; acc.z *= s; acc.w *= s;

    __stcs(&out[(long long)row * D_VEC + q * Q_VEC + sl], acc);
}

extern "C" void kernel_launch(void* const* d_in, const int* in_sizes, int n_in,
                              void* d_out, int out_size)
{
    const int*    nodes      = (const int*)d_in[0];
    const int*    neighbours = (const int*)d_in[1];
    const float4* features   = (const float4*)d_in[2];
    float4*       out        = (float4*)d_out;

    const int threads = 256;
    const int warps_needed = (B_NODES + 3) / 4;                       // 25000
    dim3 grid((warps_needed * 32 + threads - 1) / threads, 4);        // 3125 x 4
    mean_agg_kernel<<<grid, threads>>>(nodes, neighbours, features, out);
}

// round 9
// speedup vs baseline: 1.0414x; 1.0414x over previous
#include <cuda_runtime.h>
#include <stdint.h>

// MeanAggregator: out[b, :] = mean over {neighbours[b,0..9], nodes[b]} of features[idx, :]
// B = 100000, K = 10, N = 1000000, D = 128 (fp32). Indices int32 (JAX x64 disabled).
//
// Quarter D-split: per-pass distinct-row footprint 667k x 128 B = 85 MB < L2 (126 MB),
// so repeated row refs hit L2 (measured ~414 MB DRAM vs 563 MB naive). DRAM util is
// capped ~69% by the random-128B miss stream (measured R6-R8); we sit near the floor.
// This round: output stores use st.global.wt (write-through, L2 bypass) so ~13 MB/pass
// of dirty output lines stop competing with the 85 MB feature working set in L2.
//
// Warp handles 4 (row, quarter) pairs: 4 subgroups of 8 lanes, lane = float4 slot.
// Every gather is a coalesced LDG.128; 11 front-batched per lane for max MLP.

#define B_NODES   100000
#define K_NEIGH   10
#define D_DIM     128
#define D_VEC     (D_DIM / 4)    // 32 float4 per row
#define Q_VEC     8              // 8 float4 per quarter

__device__ __forceinline__ void stg_wt(float4* p, float4 v) {
    asm volatile("st.global.wt.v4.f32 [%0], {%1, %2, %3, %4};"
                 :: "l"(p), "f"(v.x), "f"(v.y), "f"(v.z), "f"(v.w)
                 : "memory");
}

__global__ __launch_bounds__(256, 4)
void mean_agg_kernel(const int*    __restrict__ nodes,
                     const int*    __restrict__ neighbours,
                     const float4* __restrict__ features,
                     float4*       __restrict__ out)
{
    const int warp = (blockIdx.x * blockDim.x + threadIdx.x) >> 5;  // 0..24999
    const int lane = threadIdx.x & 31;
    const int sub  = lane >> 3;        // subgroup 0..3 -> row offset
    const int sl   = lane & 7;         // float4 slot within quarter
    const int q    = blockIdx.y;       // feature-dim quarter (slowest-varying)

    const int row = warp * 4 + sub;
    if (row >= B_NODES) return;

    // 11 row indices for this subgroup's row (converged within subgroup).
    int idx[K_NEIGH + 1];
#pragma unroll
    for (int k = 0; k < K_NEIGH; ++k)
        idx[k] = __ldcs(&neighbours[row * K_NEIGH + k]);
    idx[K_NEIGH] = __ldcs(&nodes[row]);

    const float4* fq = features + q * Q_VEC + sl;

    // Front-batch 11 independent LDG.128 gathers for max MLP.
    float4 v[K_NEIGH + 1];
#pragma unroll
    for (int k = 0; k < K_NEIGH + 1; ++k)
        v[k] = __ldg(fq + (long long)idx[k] * D_VEC);

    float4 acc = make_float4(0.f, 0.f, 0.f, 0.f);
#pragma unroll
    for (int k = 0; k < K_NEIGH + 1; ++k) {
        acc.x += v[k].x;
        acc.y += v[k].y;
        acc.z += v[k].z;
        acc.w += v[k].w;
    }

    const float s = 1.0f / (float)(K_NEIGH + 1);
    acc.x *= s; acc.y *= s; acc.z *= s; acc.w *= s;

    stg_wt(&out[(long long)row * D_VEC + q * Q_VEC + sl], acc);
}

extern "C" void kernel_launch(void* const* d_in, const int* in_sizes, int n_in,
                              void* d_out, int out_size)
{
    const int*    nodes      = (const int*)d_in[0];
    const int*    neighbours = (const int*)d_in[1];
    const float4* features   = (const float4*)d_in[2];
    float4*       out        = (float4*)d_out;

    const int threads = 256;
    const int warps_needed = (B_NODES + 3) / 4;                       // 25000
    dim3 grid((warps_needed * 32 + threads - 1) / threads, 4);        // 3125 x 4
    mean_agg_kernel<<<grid, threads>>>(nodes, neighbours, features, out);
}

// round 10
// speedup vs baseline: 1.0436x; 1.0021x over previous
#include <cuda_runtime.h>
#include <stdint.h>

// MeanAggregator: out[b, :] = mean over {neighbours[b,0..9], nodes[b]} of features[idx, :]
// B = 100000, K = 10, N = 1000000, D = 128 (fp32). Indices int32 (JAX x64 disabled).
//
// HALF D-split probe: 2 passes over 64-float halves (256 B per row per pass).
// Footprint 667k x 256 B = 171 MB > L2 (126 MB) -> partial repeat hits (~2/3),
// but misses are 256B-contiguous, which should lift DRAM efficiency toward the
// 81% measured for 512B-grain (R2) from the 70% measured for 128B-grain (R6-R9).
//
// Warp = 2 rows: 2 subgroups of 16 lanes; lane covers one float4 of the 16-float4
// half-row. Every gather is a coalesced 256B (2-line) read per subgroup.
// 11 gathers front-batched per lane for max MLP. Output via st.global.wt.

#define B_NODES   100000
#define K_NEIGH   10
#define D_DIM     128
#define D_VEC     (D_DIM / 4)    // 32 float4 per row
#define H_VEC     16             // 16 float4 per half

__device__ __forceinline__ void stg_wt(float4* p, float4 v) {
    asm volatile("st.global.wt.v4.f32 [%0], {%1, %2, %3, %4};"
                 :: "l"(p), "f"(v.x), "f"(v.y), "f"(v.z), "f"(v.w)
                 : "memory");
}

__global__ __launch_bounds__(256, 4)
void mean_agg_kernel(const int*    __restrict__ nodes,
                     const int*    __restrict__ neighbours,
                     const float4* __restrict__ features,
                     float4*       __restrict__ out)
{
    const int warp = (blockIdx.x * blockDim.x + threadIdx.x) >> 5;  // 0..49999
    const int lane = threadIdx.x & 31;
    const int sub  = lane >> 4;        // subgroup 0..1 -> row offset
    const int sl   = lane & 15;        // float4 slot within half-row
    const int q    = blockIdx.y;       // feature-dim half (slowest-varying)

    const int row = warp * 2 + sub;
    if (row >= B_NODES) return;

    // 11 row indices for this subgroup's row (converged within subgroup).
    int idx[K_NEIGH + 1];
#pragma unroll
    for (int k = 0; k < K_NEIGH; ++k)
        idx[k] = __ldcs(&neighbours[row * K_NEIGH + k]);
    idx[K_NEIGH] = __ldcs(&nodes[row]);

    const float4* fq = features + q * H_VEC + sl;

    // Front-batch 11 independent LDG.128 gathers (256B contiguous per subgroup).
    float4 v[K_NEIGH + 1];
#pragma unroll
    for (int k = 0; k < K_NEIGH + 1; ++k)
        v[k] = __ldg(fq + (long long)idx[k] * D_VEC);

    float4 acc = make_float4(0.f, 0.f, 0.f, 0.f);
#pragma unroll
    for (int k = 0; k < K_NEIGH + 1; ++k) {
        acc.x += v[k].x;
        acc.y += v[k].y;
        acc.z += v[k].z;
        acc.w += v[k].w;
    }

    const float s = 1.0f / (float)(K_NEIGH + 1);
    acc.x *= s; acc.y *= s; acc.z *= s; acc.w *= s;

    stg_wt(&out[(long long)row * D_VEC + q * H_VEC + sl], acc);
}

extern "C" void kernel_launch(void* const* d_in, const int* in_sizes, int n_in,
                              void* d_out, int out_size)
{
    const int*    nodes      = (const int*)d_in[0];
    const int*    neighbours = (const int*)d_in[1];
    const float4* features   = (const float4*)d_in[2];
    float4*       out        = (float4*)d_out;

    const int threads = 256;
    const int warps_needed = (B_NODES + 1) / 2;                       // 50000
    dim3 grid((warps_needed * 32 + threads - 1) / threads, 2);        // 6250 x 2
    mean_agg_kernel<<<grid, threads>>>(nodes, neighbours, features, out);
}